// round 5
// baseline (speedup 1.0000x reference)
#include <cuda_runtime.h>
#include <cstdint>
#include <climits>

#define MARGIN 0.2f
#define EPSV   1e-6f
#define MAX_IDS 65536
#define MAIN_BLOCKS 1184   // 148 SMs x 8 blocks
#define MAIN_THREADS 256

__device__ int   g_first[MAX_IDS];
__device__ int   g_second[MAX_IDS];
__device__ int   g_j0;          // first index with id != ids[0]
__device__ float g_total;
__device__ int   g_count;
__device__ unsigned int g_done;

// ---------------- kernel 1: init ----------------
__global__ void k_init() {
    int i = blockIdx.x * blockDim.x + threadIdx.x;
    if (i < MAX_IDS) {
        g_first[i]  = INT_MAX;
        g_second[i] = INT_MAX;
    }
    if (i == 0) {
        g_j0    = INT_MAX;
        g_total = 0.0f;
        g_count = 0;
        g_done  = 0;
    }
}

// ---------------- kernel 2: fused first+second occurrence + j0 ----------------
// Two-smallest trick: when atomicMin displaces (or rejects) a value, the loser
// is a candidate for the second-smallest.
__global__ void k_pass(const int* __restrict__ ids, int B) {
    int i = blockIdx.x * blockDim.x + threadIdx.x;
    if (i >= B) return;
    int id  = ids[i] & (MAX_IDS - 1);
    int id0 = ids[0] & (MAX_IDS - 1);
    int old = atomicMin(&g_first[id], i);
    if (old != INT_MAX) {
        int c = (i > old) ? i : old;     // max(i, old) = loser of the min
        atomicMin(&g_second[id], c);
    }
    if (id != id0) atomicMin(&g_j0, i);
}

// ---------------- kernel 3: main — persistent warps + last-block finalize ----
__global__ void __launch_bounds__(MAIN_THREADS, 8)
k_main(const float* __restrict__ P,
       const int* __restrict__ ids,
       int B, int D,
       float* __restrict__ out) {
    const int lane       = threadIdx.x & 31;
    const int wid_blk    = threadIdx.x >> 5;
    const int nwarps_blk = MAIN_THREADS >> 5;
    const int gwarp      = (blockIdx.x * MAIN_THREADS + threadIdx.x) >> 5;
    const int warp_total = MAIN_BLOCKS * nwarps_blk;

    __shared__ float s_sum[8];
    __shared__ int   s_cnt[8];

    const int id0 = ids[0] & (MAX_IDS - 1);
    const int j0  = g_j0;

    float acc = 0.0f;   // full warp-sum replicated on all lanes
    int   cnt = 0;

    for (int i = gwarp; i < B; i += warp_total) {
        int id = ids[i] & (MAX_IDS - 1);
        int f  = g_first[id];
        int s  = g_second[id];

        bool has_pos = (s != INT_MAX);
        int  pos_idx = (f != i) ? f : s;

        int  neg_idx = (id != id0) ? 0 : j0;
        bool has_neg = (id != id0) || (j0 != INT_MAX);

        if (has_pos && has_neg) {
            const float* pa = P + (size_t)i       * D;
            const float* pb = P + (size_t)pos_idx * D;
            const float* pc = P + (size_t)neg_idx * D;
            float dp = 0.0f, dn = 0.0f;
            for (int base = lane * 4; base < D; base += 128) {
                float4 a = *(const float4*)(pa + base);
                float4 b = *(const float4*)(pb + base);
                float4 c = *(const float4*)(pc + base);
                float t;
                t = a.x - b.x + EPSV; dp += t * t;
                t = a.y - b.y + EPSV; dp += t * t;
                t = a.z - b.z + EPSV; dp += t * t;
                t = a.w - b.w + EPSV; dp += t * t;
                t = a.x - c.x + EPSV; dn += t * t;
                t = a.y - c.y + EPSV; dn += t * t;
                t = a.z - c.z + EPSV; dn += t * t;
                t = a.w - c.w + EPSV; dn += t * t;
            }
            #pragma unroll
            for (int off = 16; off > 0; off >>= 1) {
                dp += __shfl_xor_sync(0xFFFFFFFFu, dp, off);
                dn += __shfl_xor_sync(0xFFFFFFFFu, dn, off);
            }
            float v = sqrtf(dp) - sqrtf(dn) + MARGIN;
            acc += (v > 0.0f) ? v : 0.0f;
            cnt += 1;
        }
    }

    // block reduction (acc/cnt are uniform across the warp; lane 0 deposits)
    if (lane == 0) { s_sum[wid_blk] = acc; s_cnt[wid_blk] = cnt; }
    __syncthreads();
    if (wid_blk == 0) {
        float v = (lane < nwarps_blk) ? s_sum[lane] : 0.0f;
        int   c = (lane < nwarps_blk) ? s_cnt[lane] : 0;
        #pragma unroll
        for (int off = 4; off > 0; off >>= 1) {
            v += __shfl_xor_sync(0xFFFFFFFFu, v, off);
            c += __shfl_xor_sync(0xFFFFFFFFu, c, off);
        }
        if (lane == 0) {
            atomicAdd(&g_total, v);
            atomicAdd(&g_count, c);
            __threadfence();
            unsigned int ticket = atomicAdd(&g_done, 1u);
            if (ticket == MAIN_BLOCKS - 1) {
                // all blocks' contributions visible
                float tot = g_total;
                int   n   = g_count;
                out[0] = tot / (float)(n > 0 ? n : 1);
            }
        }
    }
}

extern "C" void kernel_launch(void* const* d_in, const int* in_sizes, int n_in,
                              void* d_out, int out_size) {
    const float* P   = (const float*)d_in[0];
    const int*   ids = (const int*)d_in[1];
    float*       out = (float*)d_out;

    int B = in_sizes[1];
    int D = in_sizes[0] / B;

    k_init<<<(MAX_IDS + 255) / 256, 256>>>();
    k_pass<<<(B + 255) / 256, 256>>>(ids, B);
    k_main<<<MAIN_BLOCKS, MAIN_THREADS>>>(P, ids, B, D, out);
}